// round 16
// baseline (speedup 1.0000x reference)
#include <cuda_runtime.h>
#include <cuda_bf16.h>
#include <math.h>
#include <stdint.h>

// Problem constants
#define PB 16
#define PN 512
#define PF 64
#define PT 24
#define PO 64
#define PDI 128
#define PDS 16
#define PJ (PO*PT)   // 1536
#define TPAD 136     // smem tile row pitch (floats): conflict-free fragment loads

// ---------------- scratch buffers ----------------
__device__ float g_lhs[PB*PN*PT];
__device__ float g_rhs[PB*PN*PT];
__device__ float g_sig[(size_t)PB*PN*PN];
__device__ float g_S  [(size_t)PB*PN*PN];
__device__ float g_diag[PB*PN];   // UNNORMALIZED exp at (n,n)
__device__ float g_inv [PB*PN];   // 1/sum per column
__device__ float g_xTh0[(size_t)PB*PN*PJ];
__device__ float g_xTh1[(size_t)PB*PN*PJ];
__device__ float g_xTh2[(size_t)PB*PN*PJ];
__device__ float g_xgcn[(size_t)PB*PN*PJ];

// ---------------- TF32 helpers ----------------
__device__ __forceinline__ uint32_t f2tf32(float x) {
    uint32_t r; asm("cvt.rna.tf32.f32 %0, %1;" : "=r"(r) : "f"(x)); return r;
}
__device__ __forceinline__ void mma_tf32(float& d0, float& d1, float& d2, float& d3,
                                         uint32_t a0, uint32_t a1, uint32_t a2, uint32_t a3,
                                         uint32_t b0, uint32_t b1) {
    asm volatile("mma.sync.aligned.m16n8k8.row.col.f32.tf32.tf32.f32 "
                 "{%0,%1,%2,%3}, {%4,%5,%6,%7}, {%8,%9}, {%0,%1,%2,%3};"
                 : "+f"(d0), "+f"(d1), "+f"(d2), "+f"(d3)
                 : "r"(a0), "r"(a1), "r"(a2), "r"(a3), "r"(b0), "r"(b1));
}

// ---------------- K1: lhs/rhs per (b,n) ----------------
__global__ void k1_lhs_rhs(const float* __restrict__ x, const float* __restrict__ W1,
                           const float* __restrict__ W2, const float* __restrict__ W3) {
    int bn = blockIdx.x;
    __shared__ float xs[PF*PT];
    __shared__ float xl[PF];
    const float* xp = x + (size_t)bn * PF * PT;
    for (int i = threadIdx.x; i < PF*PT; i += 64) xs[i] = xp[i];
    __syncthreads();
    int f = threadIdx.x;
    float a = 0.f;
    #pragma unroll
    for (int t = 0; t < PT; t++) a += xs[f*PT + t] * W1[t];
    xl[f] = a;
    __syncthreads();
    if (threadIdx.x < PT) {
        int t = threadIdx.x;
        float l = 0.f, r = 0.f;
        for (int f2 = 0; f2 < PF; f2++) {
            l += xl[f2] * W2[f2*PT + t];
            r += W3[f2] * xs[f2*PT + t];
        }
        g_lhs[bn*PT + t] = l;
        g_rhs[bn*PT + t] = r;
    }
}

// ---------------- K2: prod = lhs @ rhs^T (K=24), + bsp, sigmoid ----------------
__global__ void k2_prod_sig(const float* __restrict__ bsp) {
    int b = blockIdx.z;
    int n0 = blockIdx.y * 64;
    int m0 = blockIdx.x * 64;
    __shared__ float Ls[64*25];
    __shared__ float Rs[64*25];
    const float* lp = g_lhs + (size_t)(b*PN + n0) * PT;
    const float* rp = g_rhs + (size_t)(b*PN + m0) * PT;
    for (int i = threadIdx.x; i < 64*PT; i += 256) {
        int row = i / PT, col = i % PT;
        Ls[row*25 + col] = lp[i];
        Rs[row*25 + col] = rp[i];
    }
    __syncthreads();
    int tn = (threadIdx.x >> 4) * 4;
    int tm = (threadIdx.x & 15) * 4;
    float acc[4][4];
    #pragma unroll
    for (int i = 0; i < 4; i++)
        #pragma unroll
        for (int j = 0; j < 4; j++) acc[i][j] = 0.f;
    #pragma unroll
    for (int t = 0; t < PT; t++) {
        float lv[4], rv[4];
        #pragma unroll
        for (int i = 0; i < 4; i++) { lv[i] = Ls[(tn+i)*25 + t]; rv[i] = Rs[(tm+i)*25 + t]; }
        #pragma unroll
        for (int i = 0; i < 4; i++)
            #pragma unroll
            for (int j = 0; j < 4; j++) acc[i][j] += lv[i]*rv[j];
    }
    #pragma unroll
    for (int i = 0; i < 4; i++) {
        int n = n0 + tn + i;
        float4 ov;
        float* pv = (float*)&ov;
        #pragma unroll
        for (int j = 0; j < 4; j++) {
            int m = m0 + tm + j;
            float p = acc[i][j] + bsp[n*PN + m];
            pv[j] = 1.f / (1.f + __expf(-p));
        }
        *(float4*)&g_sig[((size_t)b*PN + n)*PN + m0 + tm] = ov;
    }
}

// ---------------- K3: Sg[b] = Vs @ sig[b]  (fp32 NN GEMM) ----------------
__global__ __launch_bounds__(256, 2) void k3_vs_gemm(const float* __restrict__ Vs) {
    int b = blockIdx.z;
    int i0 = blockIdx.y * 128;
    int j0 = blockIdx.x * 128;
    __shared__ float As[8][128];
    __shared__ float Bs[8][128];
    int tid = threadIdx.x;
    int ty = tid >> 4, tx = tid & 15;
    int ir = tid >> 1;
    int kq = (tid & 1) * 4;
    int lr = tid >> 5;
    int lc = (tid & 31) * 4;
    const float* Bbase = g_sig + (size_t)b * PN * PN;
    float acc[8][8];
    #pragma unroll
    for (int r = 0; r < 8; r++)
        #pragma unroll
        for (int c = 0; c < 8; c++) acc[r][c] = 0.f;

    for (int k0 = 0; k0 < PN; k0 += 8) {
        float4 av = *(const float4*)(Vs + (size_t)(i0 + ir)*PN + k0 + kq);
        float4 bv = *(const float4*)(Bbase + (size_t)(k0 + lr)*PN + j0 + lc);
        __syncthreads();
        As[kq+0][ir] = av.x; As[kq+1][ir] = av.y; As[kq+2][ir] = av.z; As[kq+3][ir] = av.w;
        *(float4*)&Bs[lr][lc] = bv;
        __syncthreads();
        #pragma unroll
        for (int kk = 0; kk < 8; kk++) {
            float a[8], bb[8];
            *(float4*)&a[0]  = *(const float4*)&As[kk][ty*4];
            *(float4*)&a[4]  = *(const float4*)&As[kk][64 + ty*4];
            *(float4*)&bb[0] = *(const float4*)&Bs[kk][tx*4];
            *(float4*)&bb[4] = *(const float4*)&Bs[kk][64 + tx*4];
            #pragma unroll
            for (int r = 0; r < 8; r++)
                #pragma unroll
                for (int c = 0; c < 8; c++) acc[r][c] += a[r]*bb[c];
        }
    }
    #pragma unroll
    for (int rh = 0; rh < 2; rh++)
        #pragma unroll
        for (int r4 = 0; r4 < 4; r4++) {
            int i = i0 + rh*64 + ty*4 + r4;
            float* op = g_S + ((size_t)b*PN + i)*PN + j0;
            #pragma unroll
            for (int ch = 0; ch < 2; ch++) {
                float4 ov;
                ov.x = acc[rh*4+r4][ch*4+0];
                ov.y = acc[rh*4+r4][ch*4+1];
                ov.z = acc[rh*4+r4][ch*4+2];
                ov.w = acc[rh*4+r4][ch*4+3];
                *(float4*)(op + ch*64 + tx*4) = ov;
            }
        }
}

// ---------------- K4: column max + exp + sum (NO normalize pass) ----------------
// Leaves g_S as exp(S - colmax) unnormalized; g_inv = 1/sum, g_diag = exp at (k,k).
__global__ void k4_softmax() {
    int b = blockIdx.y;
    int k = blockIdx.x * 128 + threadIdx.x;
    size_t base = (size_t)b * PN * PN + k;
    float mx = -1e30f;
    for (int n = 0; n < PN; n += 8) {
        float v0 = g_S[base + (size_t)(n+0)*PN];
        float v1 = g_S[base + (size_t)(n+1)*PN];
        float v2 = g_S[base + (size_t)(n+2)*PN];
        float v3 = g_S[base + (size_t)(n+3)*PN];
        float v4 = g_S[base + (size_t)(n+4)*PN];
        float v5 = g_S[base + (size_t)(n+5)*PN];
        float v6 = g_S[base + (size_t)(n+6)*PN];
        float v7 = g_S[base + (size_t)(n+7)*PN];
        mx = fmaxf(mx, fmaxf(fmaxf(fmaxf(v0,v1),fmaxf(v2,v3)), fmaxf(fmaxf(v4,v5),fmaxf(v6,v7))));
    }
    float sum = 0.f, dv = 0.f;
    for (int n = 0; n < PN; n += 4) {
        float e0 = __expf(g_S[base + (size_t)(n+0)*PN] - mx);
        float e1 = __expf(g_S[base + (size_t)(n+1)*PN] - mx);
        float e2 = __expf(g_S[base + (size_t)(n+2)*PN] - mx);
        float e3 = __expf(g_S[base + (size_t)(n+3)*PN] - mx);
        g_S[base + (size_t)(n+0)*PN] = e0;
        g_S[base + (size_t)(n+1)*PN] = e1;
        g_S[base + (size_t)(n+2)*PN] = e2;
        g_S[base + (size_t)(n+3)*PN] = e3;
        sum += (e0 + e1) + (e2 + e3);
        if (n + 0 == k) dv = e0;
        if (n + 1 == k) dv = e1;
        if (n + 2 == k) dv = e2;
        if (n + 3 == k) dv = e3;
    }
    g_diag[b*PN + k] = dv;
    g_inv [b*PN + k] = 1.f / sum;
}

// ---------------- K6: xTh_k[b][m][o*24+t] = sum_f x[b,m,f,t] * Theta[k,f,o] ----------------
__global__ void k6_xtheta(const float* __restrict__ x, const float* __restrict__ Theta) {
    int bn = blockIdx.x;
    __shared__ float xs[PF*PT];
    __shared__ float Th[PF*PO];
    int tid = threadIdx.x;
    const float* xp = x + (size_t)bn * PF * PT;
    for (int i = tid; i < PF*PT; i += 256) xs[i] = xp[i];
    int o = tid & 63, tq = tid >> 6;
    int t0 = tq * 6;
    for (int k = 0; k < 3; k++) {
        __syncthreads();
        for (int i = tid; i < PF*PO; i += 256) Th[i] = Theta[k*PF*PO + i];
        __syncthreads();
        float acc[6] = {0.f,0.f,0.f,0.f,0.f,0.f};
        for (int f = 0; f < PF; f++) {
            float th = Th[f*PO + o];
            const float* xr = &xs[f*PT + t0];
            #pragma unroll
            for (int c = 0; c < 6; c++) acc[c] += th * xr[c];
        }
        float* op = (k == 0 ? g_xTh0 : (k == 1 ? g_xTh1 : g_xTh2)) + (size_t)bn*PJ + o*PT + t0;
        #pragma unroll
        for (int c = 0; c < 6; c++) op[c] = acc[c];
    }
}

// ---------------- K7: GCN dual GEMM on TF32 tensor cores + fused normalize/diag/ReLU ----------------
// unnorm[n,j] = sum_m (cheb1*expS)[m,n]*xTh1[m,j] + sum_m (cheb2*expS)[m,n]*xTh2[m,j]
// xgcn[n,j]   = relu( inv[n] * (unnorm[n,j] + expDiag[n]*xTh0[n,j]) )
__global__ __launch_bounds__(256) void k7_gcn_tf32(const float* __restrict__ cheb) {
    int b = blockIdx.z;
    int i0 = blockIdx.y * 128;   // output rows n
    int j0 = blockIdx.x * 128;   // output cols j
    __shared__ float As1[8*TPAD], As2[8*TPAD], Bs1[8*TPAD], Bs2[8*TPAD];
    int tid = threadIdx.x;
    int warp = tid >> 5, lane = tid & 31;
    int lr = tid >> 5;            // 0..7 (loader row = m within chunk)
    int lc = (tid & 31) * 4;      // 0..124 (loader col)
    int warp_r = warp >> 1;       // 0..3 -> 32 rows each
    int warp_c = warp & 1;        // 0..1 -> 64 cols each
    int grp = lane >> 2, tig = lane & 3;

    const float* Sb = g_S + (size_t)b * PN * PN;       // exp values (unnormalized)
    const float* C1 = cheb + PN*PN;
    const float* C2 = cheb + 2*PN*PN;
    const float* B1 = g_xTh1 + (size_t)b * PN * PJ;
    const float* B2 = g_xTh2 + (size_t)b * PN * PJ;

    float acc[2][8][4];           // [row-tile][col-tile][frag]
    #pragma unroll
    for (int r = 0; r < 2; r++)
        #pragma unroll
        for (int c = 0; c < 8; c++)
            #pragma unroll
            for (int q = 0; q < 4; q++) acc[r][c][q] = 0.f;

    for (int k0 = 0; k0 < PN; k0 += 8) {
        size_t arow = (size_t)(k0+lr)*PN + i0 + lc;
        float4 sv = *(const float4*)(Sb + arow);
        float4 c1 = *(const float4*)(C1 + arow);
        float4 c2 = *(const float4*)(C2 + arow);
        float4 b1 = *(const float4*)(B1 + (size_t)(k0+lr)*PJ + j0 + lc);
        float4 b2 = *(const float4*)(B2 + (size_t)(k0+lr)*PJ + j0 + lc);
        __syncthreads();
        float* a1p = &As1[lr*TPAD + lc];
        float* a2p = &As2[lr*TPAD + lc];
        float* b1p = &Bs1[lr*TPAD + lc];
        float* b2p = &Bs2[lr*TPAD + lc];
        a1p[0] = __uint_as_float(f2tf32(c1.x*sv.x));
        a1p[1] = __uint_as_float(f2tf32(c1.y*sv.y));
        a1p[2] = __uint_as_float(f2tf32(c1.z*sv.z));
        a1p[3] = __uint_as_float(f2tf32(c1.w*sv.w));
        a2p[0] = __uint_as_float(f2tf32(c2.x*sv.x));
        a2p[1] = __uint_as_float(f2tf32(c2.y*sv.y));
        a2p[2] = __uint_as_float(f2tf32(c2.z*sv.z));
        a2p[3] = __uint_as_float(f2tf32(c2.w*sv.w));
        b1p[0] = __uint_as_float(f2tf32(b1.x));
        b1p[1] = __uint_as_float(f2tf32(b1.y));
        b1p[2] = __uint_as_float(f2tf32(b1.z));
        b1p[3] = __uint_as_float(f2tf32(b1.w));
        b2p[0] = __uint_as_float(f2tf32(b2.x));
        b2p[1] = __uint_as_float(f2tf32(b2.y));
        b2p[2] = __uint_as_float(f2tf32(b2.z));
        b2p[3] = __uint_as_float(f2tf32(b2.w));
        __syncthreads();

        #pragma unroll
        for (int g = 0; g < 2; g++) {
            const float* A = g ? As2 : As1;
            const float* B = g ? Bs2 : Bs1;
            uint32_t afr[2][4];
            #pragma unroll
            for (int r = 0; r < 2; r++) {
                int rb = warp_r*32 + r*16 + grp;
                afr[r][0] = __float_as_uint(A[ tig     *TPAD + rb    ]);
                afr[r][1] = __float_as_uint(A[ tig     *TPAD + rb + 8]);
                afr[r][2] = __float_as_uint(A[(tig + 4)*TPAD + rb    ]);
                afr[r][3] = __float_as_uint(A[(tig + 4)*TPAD + rb + 8]);
            }
            #pragma unroll
            for (int c = 0; c < 8; c++) {
                int cb = warp_c*64 + c*8 + grp;
                uint32_t bf0 = __float_as_uint(B[ tig     *TPAD + cb]);
                uint32_t bf1 = __float_as_uint(B[(tig + 4)*TPAD + cb]);
                mma_tf32(acc[0][c][0], acc[0][c][1], acc[0][c][2], acc[0][c][3],
                         afr[0][0], afr[0][1], afr[0][2], afr[0][3], bf0, bf1);
                mma_tf32(acc[1][c][0], acc[1][c][1], acc[1][c][2], acc[1][c][3],
                         afr[1][0], afr[1][1], afr[1][2], afr[1][3], bf0, bf1);
            }
        }
    }

    // epilogue: normalize by inv[n], add diag term, relu
    #pragma unroll
    for (int r = 0; r < 2; r++) {
        int row_lo = i0 + warp_r*32 + r*16 + grp;
        int row_hi = row_lo + 8;
        float ivlo = g_inv[b*PN + row_lo], ivhi = g_inv[b*PN + row_hi];
        float edlo = g_diag[b*PN + row_lo], edhi = g_diag[b*PN + row_hi];
        const float* x0lo = g_xTh0 + ((size_t)b*PN + row_lo)*PJ;
        const float* x0hi = g_xTh0 + ((size_t)b*PN + row_hi)*PJ;
        float* oplo = g_xgcn + ((size_t)b*PN + row_lo)*PJ;
        float* ophi = g_xgcn + ((size_t)b*PN + row_hi)*PJ;
        #pragma unroll
        for (int c = 0; c < 8; c++) {
            int col = j0 + warp_c*64 + c*8 + 2*tig;
            float2 xl = *(const float2*)(x0lo + col);
            float2 xh = *(const float2*)(x0hi + col);
            float2 vl, vh;
            vl.x = fmaxf((acc[r][c][0] + edlo*xl.x) * ivlo, 0.f);
            vl.y = fmaxf((acc[r][c][1] + edlo*xl.y) * ivlo, 0.f);
            vh.x = fmaxf((acc[r][c][2] + edhi*xh.x) * ivhi, 0.f);
            vh.y = fmaxf((acc[r][c][3] + edhi*xh.y) * ivhi, 0.f);
            *(float2*)(oplo + col) = vl;
            *(float2*)(ophi + col) = vh;
        }
    }
}

// ---------------- K8: fused mamba + residual + final layernorm ----------------
__global__ __launch_bounds__(128, 5) void k8_mamba(
    const float* __restrict__ x,
    const float* __restrict__ mg, const float* __restrict__ mb,
    const float* __restrict__ Win, const float* __restrict__ conv_w, const float* __restrict__ conv_b,
    const float* __restrict__ Wxp, const float* __restrict__ Wdt, const float* __restrict__ bdt,
    const float* __restrict__ A_log, const float* __restrict__ Dp,
    const float* __restrict__ Wout, const float* __restrict__ Wres, const float* __restrict__ bres,
    const float* __restrict__ ln_g, const float* __restrict__ ln_b,
    float* __restrict__ out)
{
    int bn = blockIdx.x;
    int tid = threadIdx.x;
    int lane = tid & 31, warp = tid >> 5;
    __shared__ float xin[PT*PO];
    __shared__ float hbuf[PT*PO];
    __shared__ float xub[PT*PDI];
    __shared__ float dbc[PT*36];
    __shared__ float xg[PF*PT];
    __shared__ float red_m[PT], red_r[PT];

    const float* gx = g_xgcn + (size_t)bn * PO * PT;
    for (int i = tid; i < PO*PT; i += 128) {
        int o = i / PT, t = i % PT;
        xin[t*PO + o] = gx[i];
    }
    __syncthreads();

    for (int t = warp; t < PT; t += 4) {
        float a = xin[t*PO + lane], b2 = xin[t*PO + lane + 32];
        float s = a + b2, ss = a*a + b2*b2;
        #pragma unroll
        for (int off = 16; off; off >>= 1) {
            s  += __shfl_xor_sync(0xffffffffu, s, off);
            ss += __shfl_xor_sync(0xffffffffu, ss, off);
        }
        float m = s * (1.f/64.f);
        float v = ss * (1.f/64.f) - m*m;
        float r = rsqrtf(v + 1e-5f);
        hbuf[t*PO + lane]      = (a - m)*r*mg[lane] + mb[lane];
        hbuf[t*PO + lane + 32] = (b2 - m)*r*mg[lane+32] + mb[lane+32];
    }
    __syncthreads();

    float siluz[PT];
    {
        float accu[PT], accz[PT];
        #pragma unroll
        for (int t = 0; t < PT; t++) { accu[t] = 0.f; accz[t] = 0.f; }
        const float4* w0p = (const float4*)(Win + tid*PO);
        const float4* w1p = (const float4*)(Win + (tid+128)*PO);
        for (int oq = 0; oq < PO/4; oq++) {
            float4 w0 = w0p[oq], w1 = w1p[oq];
            #pragma unroll
            for (int t = 0; t < PT; t++) {
                float4 hv = *(const float4*)&hbuf[t*PO + oq*4];
                accu[t] += hv.x*w0.x + hv.y*w0.y + hv.z*w0.z + hv.w*w0.w;
                accz[t] += hv.x*w1.x + hv.y*w1.y + hv.z*w1.z + hv.w*w1.w;
            }
        }
        #pragma unroll
        for (int t = 0; t < PT; t++) {
            xub[t*PDI + tid] = accu[t];
            siluz[t] = accz[t] / (1.f + __expf(-accz[t]));
        }
    }

    {
        int d = tid;
        float cw0 = conv_w[d*4+0], cw1 = conv_w[d*4+1], cw2 = conv_w[d*4+2], cw3 = conv_w[d*4+3];
        float cb = conv_b[d];
        #pragma unroll
        for (int t = PT-1; t >= 0; t--) {
            float s = cb + cw3 * xub[t*PDI + d];
            if (t >= 1) s += cw2 * xub[(t-1)*PDI + d];
            if (t >= 2) s += cw1 * xub[(t-2)*PDI + d];
            if (t >= 3) s += cw0 * xub[(t-3)*PDI + d];
            xub[t*PDI + d] = s / (1.f + __expf(-s));
        }
    }
    __syncthreads();

    {
        const float4* xub4 = (const float4*)xub;
        for (int i = tid; i < PT*36; i += 128) {
            int t = i / 36, p = i % 36;
            const float4* wp = (const float4*)(Wxp + p*PDI);
            float acc = 0.f;
            #pragma unroll 8
            for (int q = 0; q < PDI/4; q++) {
                float4 xv = xub4[t*(PDI/4) + q];
                float4 wv = wp[q];
                acc += xv.x*wv.x + xv.y*wv.y + xv.z*wv.z + xv.w*wv.w;
            }
            dbc[i] = acc;
        }
    }
    __syncthreads();

    {
        int d = tid;
        float Ar[PDS];
        #pragma unroll
        for (int s = 0; s < PDS; s++) Ar[s] = -__expf(A_log[d*PDS + s]);
        float wd0 = Wdt[d*4+0], wd1 = Wdt[d*4+1], wd2 = Wdt[d*4+2], wd3 = Wdt[d*4+3];
        float bd = bdt[d];
        float dp = Dp[d];
        float h[PDS];
        #pragma unroll
        for (int s = 0; s < PDS; s++) h[s] = 0.f;
        for (int t = 0; t < PT; t++) {
            const float* dr = &dbc[t*36];
            float dtv = dr[0]*wd0 + dr[1]*wd1 + dr[2]*wd2 + dr[3]*wd3 + bd;
            float delta = (dtv > 15.f) ? dtv : log1pf(__expf(dtv));
            float u = xub[t*PDI + d];
            float du = delta * u;
            float y = 0.f;
            #pragma unroll
            for (int s = 0; s < PDS; s++) {
                float dA = __expf(delta * Ar[s]);
                h[s] = dA * h[s] + du * dr[4 + s];
                y += h[s] * dr[20 + s];
            }
            y += u * dp;
            xub[t*PDI + d] = y * siluz[t];
        }
    }
    {
        const float* xp = x + (size_t)bn * PF * PT;
        for (int i = tid; i < PF*PT; i += 128) xg[i] = xp[i];
    }
    __syncthreads();

    {
        int o = tid & 63, hf = tid >> 6;
        int t0 = hf * 12;
        float acc[12], acc2[12];
        #pragma unroll
        for (int c = 0; c < 12; c++) { acc[c] = 0.f; acc2[c] = 0.f; }
        const float4* wo4 = (const float4*)(Wout + o*PDI);
        const float4* xub4 = (const float4*)xub;
        for (int dq = 0; dq < PDI/4; dq++) {
            float4 wv = wo4[dq];
            #pragma unroll
            for (int c = 0; c < 12; c++) {
                float4 xv = xub4[(t0+c)*(PDI/4) + dq];
                acc[c] += xv.x*wv.x + xv.y*wv.y + xv.z*wv.z + xv.w*wv.w;
            }
        }
        const float* wr = Wres + o*PF;
        for (int f = 0; f < PF; f++) {
            float w = wr[f];
            float4 xv0 = *(const float4*)&xg[f*PT + t0];
            float4 xv1 = *(const float4*)&xg[f*PT + t0 + 4];
            float4 xv2 = *(const float4*)&xg[f*PT + t0 + 8];
            acc2[0] += w*xv0.x; acc2[1] += w*xv0.y; acc2[2]  += w*xv0.z; acc2[3]  += w*xv0.w;
            acc2[4] += w*xv1.x; acc2[5] += w*xv1.y; acc2[6]  += w*xv1.z; acc2[7]  += w*xv1.w;
            acc2[8] += w*xv2.x; acc2[9] += w*xv2.y; acc2[10] += w*xv2.z; acc2[11] += w*xv2.w;
        }
        float br = bres[o];
        #pragma unroll
        for (int c = 0; c < 12; c++) {
            int t = t0 + c;
            hbuf[t*PO + o] = acc[c] + acc2[c] + xin[t*PO + o] + br;
        }
    }
    __syncthreads();

    for (int t = warp; t < PT; t += 4) {
        float a = hbuf[t*PO + lane], b2 = hbuf[t*PO + lane + 32];
        float s = a + b2, ss = a*a + b2*b2;
        #pragma unroll
        for (int off = 16; off; off >>= 1) {
            s  += __shfl_xor_sync(0xffffffffu, s, off);
            ss += __shfl_xor_sync(0xffffffffu, ss, off);
        }
        if (lane == 0) {
            float m = s * (1.f/64.f);
            float v = ss * (1.f/64.f) - m*m;
            red_m[t] = m;
            red_r[t] = rsqrtf(v + 1e-5f);
        }
    }
    __syncthreads();

    float* op = out + (size_t)bn * PO * PT;
    for (int i = tid; i < PO*PT; i += 128) {
        int o = i / PT, t = i % PT;
        float v = (hbuf[t*PO + o] - red_m[t]) * red_r[t] * ln_g[o] + ln_b[o];
        op[i] = fmaxf(v, 0.f);
    }
}

// ---------------- launch ----------------
extern "C" void kernel_launch(void* const* d_in, const int* in_sizes, int n_in,
                              void* d_out, int out_size) {
    const float* x      = (const float*)d_in[0];
    const float* cheb   = (const float*)d_in[1];
    const float* W1     = (const float*)d_in[2];
    const float* W2     = (const float*)d_in[3];
    const float* W3     = (const float*)d_in[4];
    const float* bsp    = (const float*)d_in[5];
    const float* Vs     = (const float*)d_in[6];
    const float* Theta  = (const float*)d_in[7];
    const float* Wres   = (const float*)d_in[8];
    const float* bres   = (const float*)d_in[9];
    const float* mg     = (const float*)d_in[10];
    const float* mb     = (const float*)d_in[11];
    const float* Win    = (const float*)d_in[12];
    const float* conv_w = (const float*)d_in[13];
    const float* conv_b = (const float*)d_in[14];
    const float* Wxp    = (const float*)d_in[15];
    const float* Wdt    = (const float*)d_in[16];
    const float* bdt    = (const float*)d_in[17];
    const float* A_log  = (const float*)d_in[18];
    const float* Dp     = (const float*)d_in[19];
    const float* Wout   = (const float*)d_in[20];
    const float* ln_g   = (const float*)d_in[21];
    const float* ln_b   = (const float*)d_in[22];
    float* out = (float*)d_out;

    k1_lhs_rhs<<<PB*PN, 64>>>(x, W1, W2, W3);
    k2_prod_sig<<<dim3(PN/64, PN/64, PB), 256>>>(bsp);
    k3_vs_gemm<<<dim3(PN/128, PN/128, PB), 256>>>(Vs);
    k4_softmax<<<dim3(PN/128, PB), 128>>>();
    k6_xtheta<<<PB*PN, 256>>>(x, Theta);
    k7_gcn_tf32<<<dim3(PJ/128, PN/128, PB), 256>>>(cheb);
    k8_mamba<<<PB*PN, 128>>>(x, mg, mb, Win, conv_w, conv_b, Wxp, Wdt, bdt,
                             A_log, Dp, Wout, Wres, bres, ln_g, ln_b, out);
}

// round 17
// speedup vs baseline: 1.2784x; 1.2784x over previous
#include <cuda_runtime.h>
#include <cuda_bf16.h>
#include <math.h>

// Problem constants
#define PB 16
#define PN 512
#define PF 64
#define PT 24
#define PO 64
#define PDI 128
#define PDS 16
#define PJ (PO*PT)   // 1536

// ---------------- scratch buffers ----------------
__device__ float g_lhs[PB*PN*PT];
__device__ float g_rhs[PB*PN*PT];
__device__ float g_sig[(size_t)PB*PN*PN];
__device__ float g_S  [(size_t)PB*PN*PN];
__device__ float g_diag[PB*PN];   // UNNORMALIZED exp at (n,n)
__device__ float g_inv [PB*PN];   // 1/sum per column
__device__ float g_xTh0[(size_t)PB*PN*PJ];
__device__ float g_xTh1[(size_t)PB*PN*PJ];
__device__ float g_xTh2[(size_t)PB*PN*PJ];
__device__ float g_xgcn[(size_t)PB*PN*PJ];

// ---------------- K1: lhs/rhs per (b,n) ----------------
__global__ void k1_lhs_rhs(const float* __restrict__ x, const float* __restrict__ W1,
                           const float* __restrict__ W2, const float* __restrict__ W3) {
    int bn = blockIdx.x;
    __shared__ float xs[PF*PT];
    __shared__ float xl[PF];
    const float* xp = x + (size_t)bn * PF * PT;
    for (int i = threadIdx.x; i < PF*PT; i += 64) xs[i] = xp[i];
    __syncthreads();
    int f = threadIdx.x;
    float a = 0.f;
    #pragma unroll
    for (int t = 0; t < PT; t++) a += xs[f*PT + t] * W1[t];
    xl[f] = a;
    __syncthreads();
    if (threadIdx.x < PT) {
        int t = threadIdx.x;
        float l = 0.f, r = 0.f;
        for (int f2 = 0; f2 < PF; f2++) {
            l += xl[f2] * W2[f2*PT + t];
            r += W3[f2] * xs[f2*PT + t];
        }
        g_lhs[bn*PT + t] = l;
        g_rhs[bn*PT + t] = r;
    }
}

// ---------------- K2: prod = lhs @ rhs^T (K=24), + bsp, sigmoid ----------------
__global__ void k2_prod_sig(const float* __restrict__ bsp) {
    int b = blockIdx.z;
    int n0 = blockIdx.y * 64;
    int m0 = blockIdx.x * 64;
    __shared__ float Ls[64*25];
    __shared__ float Rs[64*25];
    const float* lp = g_lhs + (size_t)(b*PN + n0) * PT;
    const float* rp = g_rhs + (size_t)(b*PN + m0) * PT;
    for (int i = threadIdx.x; i < 64*PT; i += 256) {
        int row = i / PT, col = i % PT;
        Ls[row*25 + col] = lp[i];
        Rs[row*25 + col] = rp[i];
    }
    __syncthreads();
    int tn = (threadIdx.x >> 4) * 4;
    int tm = (threadIdx.x & 15) * 4;
    float acc[4][4];
    #pragma unroll
    for (int i = 0; i < 4; i++)
        #pragma unroll
        for (int j = 0; j < 4; j++) acc[i][j] = 0.f;
    #pragma unroll
    for (int t = 0; t < PT; t++) {
        float lv[4], rv[4];
        #pragma unroll
        for (int i = 0; i < 4; i++) { lv[i] = Ls[(tn+i)*25 + t]; rv[i] = Rs[(tm+i)*25 + t]; }
        #pragma unroll
        for (int i = 0; i < 4; i++)
            #pragma unroll
            for (int j = 0; j < 4; j++) acc[i][j] += lv[i]*rv[j];
    }
    #pragma unroll
    for (int i = 0; i < 4; i++) {
        int n = n0 + tn + i;
        float4 ov;
        float* pv = (float*)&ov;
        #pragma unroll
        for (int j = 0; j < 4; j++) {
            int m = m0 + tm + j;
            float p = acc[i][j] + bsp[n*PN + m];
            pv[j] = 1.f / (1.f + __expf(-p));
        }
        *(float4*)&g_sig[((size_t)b*PN + n)*PN + m0 + tm] = ov;
    }
}

// ---------------- K3: Sg[b] = Vs @ sig[b]  (fp32 NN GEMM, split-half microtile) ----------------
__global__ __launch_bounds__(256, 2) void k3_vs_gemm(const float* __restrict__ Vs) {
    int b = blockIdx.z;
    int i0 = blockIdx.y * 128;
    int j0 = blockIdx.x * 128;
    __shared__ float As[8][128];
    __shared__ float Bs[8][128];
    int tid = threadIdx.x;
    int ty = tid >> 4, tx = tid & 15;
    int ir = tid >> 1;
    int kq = (tid & 1) * 4;
    int lr = tid >> 5;
    int lc = (tid & 31) * 4;
    const float* Bbase = g_sig + (size_t)b * PN * PN;
    float acc[8][8];
    #pragma unroll
    for (int r = 0; r < 8; r++)
        #pragma unroll
        for (int c = 0; c < 8; c++) acc[r][c] = 0.f;

    for (int k0 = 0; k0 < PN; k0 += 8) {
        float4 av = *(const float4*)(Vs + (size_t)(i0 + ir)*PN + k0 + kq);
        float4 bv = *(const float4*)(Bbase + (size_t)(k0 + lr)*PN + j0 + lc);
        __syncthreads();
        As[kq+0][ir] = av.x; As[kq+1][ir] = av.y; As[kq+2][ir] = av.z; As[kq+3][ir] = av.w;
        *(float4*)&Bs[lr][lc] = bv;
        __syncthreads();
        #pragma unroll
        for (int kk = 0; kk < 8; kk++) {
            float a[8], bb[8];
            *(float4*)&a[0]  = *(const float4*)&As[kk][ty*4];
            *(float4*)&a[4]  = *(const float4*)&As[kk][64 + ty*4];
            *(float4*)&bb[0] = *(const float4*)&Bs[kk][tx*4];
            *(float4*)&bb[4] = *(const float4*)&Bs[kk][64 + tx*4];
            #pragma unroll
            for (int r = 0; r < 8; r++)
                #pragma unroll
                for (int c = 0; c < 8; c++) acc[r][c] += a[r]*bb[c];
        }
    }
    #pragma unroll
    for (int rh = 0; rh < 2; rh++)
        #pragma unroll
        for (int r4 = 0; r4 < 4; r4++) {
            int i = i0 + rh*64 + ty*4 + r4;
            float* op = g_S + ((size_t)b*PN + i)*PN + j0;
            #pragma unroll
            for (int ch = 0; ch < 2; ch++) {
                float4 ov;
                ov.x = acc[rh*4+r4][ch*4+0];
                ov.y = acc[rh*4+r4][ch*4+1];
                ov.z = acc[rh*4+r4][ch*4+2];
                ov.w = acc[rh*4+r4][ch*4+3];
                *(float4*)(op + ch*64 + tx*4) = ov;
            }
        }
}

// ---------------- K4: column max + exp + sum (NO normalize pass; validated R16) ----------------
__global__ void k4_softmax() {
    int b = blockIdx.y;
    int k = blockIdx.x * 128 + threadIdx.x;
    size_t base = (size_t)b * PN * PN + k;
    float mx = -1e30f;
    for (int n = 0; n < PN; n += 8) {
        float v0 = g_S[base + (size_t)(n+0)*PN];
        float v1 = g_S[base + (size_t)(n+1)*PN];
        float v2 = g_S[base + (size_t)(n+2)*PN];
        float v3 = g_S[base + (size_t)(n+3)*PN];
        float v4 = g_S[base + (size_t)(n+4)*PN];
        float v5 = g_S[base + (size_t)(n+5)*PN];
        float v6 = g_S[base + (size_t)(n+6)*PN];
        float v7 = g_S[base + (size_t)(n+7)*PN];
        mx = fmaxf(mx, fmaxf(fmaxf(fmaxf(v0,v1),fmaxf(v2,v3)), fmaxf(fmaxf(v4,v5),fmaxf(v6,v7))));
    }
    float sum = 0.f, dv = 0.f;
    for (int n = 0; n < PN; n += 4) {
        float e0 = __expf(g_S[base + (size_t)(n+0)*PN] - mx);
        float e1 = __expf(g_S[base + (size_t)(n+1)*PN] - mx);
        float e2 = __expf(g_S[base + (size_t)(n+2)*PN] - mx);
        float e3 = __expf(g_S[base + (size_t)(n+3)*PN] - mx);
        g_S[base + (size_t)(n+0)*PN] = e0;
        g_S[base + (size_t)(n+1)*PN] = e1;
        g_S[base + (size_t)(n+2)*PN] = e2;
        g_S[base + (size_t)(n+3)*PN] = e3;
        sum += (e0 + e1) + (e2 + e3);
        if (n + 0 == k) dv = e0;
        if (n + 1 == k) dv = e1;
        if (n + 2 == k) dv = e2;
        if (n + 3 == k) dv = e3;
    }
    g_diag[b*PN + k] = dv;
    g_inv [b*PN + k] = 1.f / sum;
}

// ---------------- K6: xTh_k[b][m][o*24+t] = sum_f x[b,m,f,t] * Theta[k,f,o] ----------------
__global__ void k6_xtheta(const float* __restrict__ x, const float* __restrict__ Theta) {
    int bn = blockIdx.x;
    __shared__ float xs[PF*PT];
    __shared__ float Th[PF*PO];
    int tid = threadIdx.x;
    const float* xp = x + (size_t)bn * PF * PT;
    for (int i = tid; i < PF*PT; i += 256) xs[i] = xp[i];
    int o = tid & 63, tq = tid >> 6;
    int t0 = tq * 6;
    for (int k = 0; k < 3; k++) {
        __syncthreads();
        for (int i = tid; i < PF*PO; i += 256) Th[i] = Theta[k*PF*PO + i];
        __syncthreads();
        float acc[6] = {0.f,0.f,0.f,0.f,0.f,0.f};
        for (int f = 0; f < PF; f++) {
            float th = Th[f*PO + o];
            const float* xr = &xs[f*PT + t0];
            #pragma unroll
            for (int c = 0; c < 6; c++) acc[c] += th * xr[c];
        }
        float* op = (k == 0 ? g_xTh0 : (k == 1 ? g_xTh1 : g_xTh2)) + (size_t)bn*PJ + o*PT + t0;
        #pragma unroll
        for (int c = 0; c < 6; c++) op[c] = acc[c];
    }
}

// ---------------- K7: fp32 GCN dual TN GEMM (validated R11) + fold epilogue (validated R16) ----------------
// unnorm[n,j] = sum_m (cheb1*expS)[m,n]*xTh1[m,j] + sum_m (cheb2*expS)[m,n]*xTh2[m,j]
// xgcn[n,j]   = relu( inv[n] * (unnorm[n,j] + expDiag[n]*xTh0[n,j]) )
__global__ __launch_bounds__(256, 2) void k7_gcn_gemm(const float* __restrict__ cheb) {
    int b = blockIdx.z;
    int i0 = blockIdx.y * 128;
    int j0 = blockIdx.x * 128;
    __shared__ float As1[8][128], As2[8][128], Bs1[8][128], Bs2[8][128];
    int tid = threadIdx.x;
    int ty = tid >> 4, tx = tid & 15;
    int lr = tid >> 5;
    int lc = (tid & 31) * 4;
    const float* Sb = g_S + (size_t)b * PN * PN;   // exp values (unnormalized)
    const float* C1 = cheb + PN*PN;
    const float* C2 = cheb + 2*PN*PN;
    const float* B1 = g_xTh1 + (size_t)b * PN * PJ;
    const float* B2 = g_xTh2 + (size_t)b * PN * PJ;
    float acc[8][8];
    #pragma unroll
    for (int r = 0; r < 8; r++)
        #pragma unroll
        for (int c = 0; c < 8; c++) acc[r][c] = 0.f;

    for (int k0 = 0; k0 < PN; k0 += 8) {
        size_t arow = (size_t)(k0+lr)*PN + i0 + lc;
        float4 sv = *(const float4*)(Sb + arow);
        float4 c1 = *(const float4*)(C1 + arow);
        float4 c2 = *(const float4*)(C2 + arow);
        float4 b1 = *(const float4*)(B1 + (size_t)(k0+lr)*PJ + j0 + lc);
        float4 b2 = *(const float4*)(B2 + (size_t)(k0+lr)*PJ + j0 + lc);
        float4 a1, a2;
        a1.x = c1.x*sv.x; a1.y = c1.y*sv.y; a1.z = c1.z*sv.z; a1.w = c1.w*sv.w;
        a2.x = c2.x*sv.x; a2.y = c2.y*sv.y; a2.z = c2.z*sv.z; a2.w = c2.w*sv.w;
        __syncthreads();
        *(float4*)&As1[lr][lc] = a1;
        *(float4*)&As2[lr][lc] = a2;
        *(float4*)&Bs1[lr][lc] = b1;
        *(float4*)&Bs2[lr][lc] = b2;
        __syncthreads();
        #pragma unroll
        for (int kk = 0; kk < 8; kk++) {
            float av1[8], bv1[8], av2[8], bv2[8];
            *(float4*)&av1[0] = *(const float4*)&As1[kk][ty*4];
            *(float4*)&av1[4] = *(const float4*)&As1[kk][64 + ty*4];
            *(float4*)&av2[0] = *(const float4*)&As2[kk][ty*4];
            *(float4*)&av2[4] = *(const float4*)&As2[kk][64 + ty*4];
            *(float4*)&bv1[0] = *(const float4*)&Bs1[kk][tx*4];
            *(float4*)&bv1[4] = *(const float4*)&Bs1[kk][64 + tx*4];
            *(float4*)&bv2[0] = *(const float4*)&Bs2[kk][tx*4];
            *(float4*)&bv2[4] = *(const float4*)&Bs2[kk][64 + tx*4];
            #pragma unroll
            for (int r = 0; r < 8; r++)
                #pragma unroll
                for (int c = 0; c < 8; c++)
                    acc[r][c] += av1[r]*bv1[c] + av2[r]*bv2[c];
        }
    }
    #pragma unroll
    for (int rh = 0; rh < 2; rh++)
        #pragma unroll
        for (int r4 = 0; r4 < 4; r4++) {
            int i = i0 + rh*64 + ty*4 + r4;
            float dv = g_diag[b*PN + i];
            float iv = g_inv[b*PN + i];
            const float* x0 = g_xTh0 + ((size_t)b*PN + i)*PJ + j0;
            float* op = g_xgcn + ((size_t)b*PN + i)*PJ + j0;
            #pragma unroll
            for (int ch = 0; ch < 2; ch++) {
                float4 xv = *(const float4*)(x0 + ch*64 + tx*4);
                float4 ov;
                ov.x = fmaxf((acc[rh*4+r4][ch*4+0] + dv*xv.x) * iv, 0.f);
                ov.y = fmaxf((acc[rh*4+r4][ch*4+1] + dv*xv.y) * iv, 0.f);
                ov.z = fmaxf((acc[rh*4+r4][ch*4+2] + dv*xv.z) * iv, 0.f);
                ov.w = fmaxf((acc[rh*4+r4][ch*4+3] + dv*xv.w) * iv, 0.f);
                *(float4*)(op + ch*64 + tx*4) = ov;
            }
        }
}

// ---------------- K8: fused mamba + residual + final layernorm (validated R11) ----------------
__global__ __launch_bounds__(128, 5) void k8_mamba(
    const float* __restrict__ x,
    const float* __restrict__ mg, const float* __restrict__ mb,
    const float* __restrict__ Win, const float* __restrict__ conv_w, const float* __restrict__ conv_b,
    const float* __restrict__ Wxp, const float* __restrict__ Wdt, const float* __restrict__ bdt,
    const float* __restrict__ A_log, const float* __restrict__ Dp,
    const float* __restrict__ Wout, const float* __restrict__ Wres, const float* __restrict__ bres,
    const float* __restrict__ ln_g, const float* __restrict__ ln_b,
    float* __restrict__ out)
{
    int bn = blockIdx.x;
    int tid = threadIdx.x;
    int lane = tid & 31, warp = tid >> 5;
    __shared__ float xin[PT*PO];
    __shared__ float hbuf[PT*PO];
    __shared__ float xub[PT*PDI];
    __shared__ float dbc[PT*36];
    __shared__ float xg[PF*PT];
    __shared__ float red_m[PT], red_r[PT];

    const float* gx = g_xgcn + (size_t)bn * PO * PT;
    for (int i = tid; i < PO*PT; i += 128) {
        int o = i / PT, t = i % PT;
        xin[t*PO + o] = gx[i];
    }
    __syncthreads();

    for (int t = warp; t < PT; t += 4) {
        float a = xin[t*PO + lane], b2 = xin[t*PO + lane + 32];
        float s = a + b2, ss = a*a + b2*b2;
        #pragma unroll
        for (int off = 16; off; off >>= 1) {
            s  += __shfl_xor_sync(0xffffffffu, s, off);
            ss += __shfl_xor_sync(0xffffffffu, ss, off);
        }
        float m = s * (1.f/64.f);
        float v = ss * (1.f/64.f) - m*m;
        float r = rsqrtf(v + 1e-5f);
        hbuf[t*PO + lane]      = (a - m)*r*mg[lane] + mb[lane];
        hbuf[t*PO + lane + 32] = (b2 - m)*r*mg[lane+32] + mb[lane+32];
    }
    __syncthreads();

    float siluz[PT];
    {
        float accu[PT], accz[PT];
        #pragma unroll
        for (int t = 0; t < PT; t++) { accu[t] = 0.f; accz[t] = 0.f; }
        const float4* w0p = (const float4*)(Win + tid*PO);
        const float4* w1p = (const float4*)(Win + (tid+128)*PO);
        for (int oq = 0; oq < PO/4; oq++) {
            float4 w0 = w0p[oq], w1 = w1p[oq];
            #pragma unroll
            for (int t = 0; t < PT; t++) {
                float4 hv = *(const float4*)&hbuf[t*PO + oq*4];
                accu[t] += hv.x*w0.x + hv.y*w0.y + hv.z*w0.z + hv.w*w0.w;
                accz[t] += hv.x*w1.x + hv.y*w1.y + hv.z*w1.z + hv.w*w1.w;
            }
        }
        #pragma unroll
        for (int t = 0; t < PT; t++) {
            xub[t*PDI + tid] = accu[t];
            siluz[t] = accz[t] / (1.f + __expf(-accz[t]));
        }
    }

    {
        int d = tid;
        float cw0 = conv_w[d*4+0], cw1 = conv_w[d*4+1], cw2 = conv_w[d*4+2], cw3 = conv_w[d*4+3];
        float cb = conv_b[d];
        #pragma unroll
        for (int t = PT-1; t >= 0; t--) {
            float s = cb + cw3 * xub[t*PDI + d];
            if (t >= 1) s += cw2 * xub[(t-1)*PDI + d];
            if (t >= 2) s += cw1 * xub[(t-2)*PDI + d];
            if (t >= 3) s += cw0 * xub[(t-3)*PDI + d];
            xub[t*PDI + d] = s / (1.f + __expf(-s));
        }
    }
    __syncthreads();

    {
        const float4* xub4 = (const float4*)xub;
        for (int i = tid; i < PT*36; i += 128) {
            int t = i / 36, p = i % 36;
            const float4* wp = (const float4*)(Wxp + p*PDI);
            float acc = 0.f;
            #pragma unroll 8
            for (int q = 0; q < PDI/4; q++) {
                float4 xv = xub4[t*(PDI/4) + q];
                float4 wv = wp[q];
                acc += xv.x*wv.x + xv.y*wv.y + xv.z*wv.z + xv.w*wv.w;
            }
            dbc[i] = acc;
        }
    }
    __syncthreads();

    {
        int d = tid;
        float Ar[PDS];
        #pragma unroll
        for (int s = 0; s < PDS; s++) Ar[s] = -__expf(A_log[d*PDS + s]);
        float wd0 = Wdt[d*4+0], wd1 = Wdt[d*4+1], wd2 = Wdt[d*4+2], wd3 = Wdt[d*4+3];
        float bd = bdt[d];
        float dp = Dp[d];
        float h[PDS];
        #pragma unroll
        for (int s = 0; s < PDS; s++) h[s] = 0.f;
        for (int t = 0; t < PT; t++) {
            const float* dr = &dbc[t*36];
            float dtv = dr[0]*wd0 + dr[1]*wd1 + dr[2]*wd2 + dr[3]*wd3 + bd;
            float delta = (dtv > 15.f) ? dtv : log1pf(__expf(dtv));
            float u = xub[t*PDI + d];
            float du = delta * u;
            float y = 0.f;
            #pragma unroll
            for (int s = 0; s < PDS; s++) {
                float dA = __expf(delta * Ar[s]);
                h[s] = dA * h[s] + du * dr[4 + s];
                y += h[s] * dr[20 + s];
            }
            y += u * dp;
            xub[t*PDI + d] = y * siluz[t];
        }
    }
    {
        const float* xp = x + (size_t)bn * PF * PT;
        for (int i = tid; i < PF*PT; i += 128) xg[i] = xp[i];
    }
    __syncthreads();

    {
        int o = tid & 63, hf = tid >> 6;
        int t0 = hf * 12;
        float acc[12], acc2[12];
        #pragma unroll
        for (int c = 0; c < 12; c++) { acc[c] = 0.f; acc2[c] = 0.f; }
        const float4* wo4 = (const float4*)(Wout + o*PDI);
        const float4* xub4 = (const float4*)xub;
        for (int dq = 0; dq < PDI/4; dq++) {
            float4 wv = wo4[dq];
            #pragma unroll
            for (int c = 0; c < 12; c++) {
                float4 xv = xub4[(t0+c)*(PDI/4) + dq];
                acc[c] += xv.x*wv.x + xv.y*wv.y + xv.z*wv.z + xv.w*wv.w;
            }
        }
        const float* wr = Wres + o*PF;
        for (int f = 0; f < PF; f++) {
            float w = wr[f];
            float4 xv0 = *(const float4*)&xg[f*PT + t0];
            float4 xv1 = *(const float4*)&xg[f*PT + t0 + 4];
            float4 xv2 = *(const float4*)&xg[f*PT + t0 + 8];
            acc2[0] += w*xv0.x; acc2[1] += w*xv0.y; acc2[2]  += w*xv0.z; acc2[3]  += w*xv0.w;
            acc2[4] += w*xv1.x; acc2[5] += w*xv1.y; acc2[6]  += w*xv1.z; acc2[7]  += w*xv1.w;
            acc2[8] += w*xv2.x; acc2[9] += w*xv2.y; acc2[10] += w*xv2.z; acc2[11] += w*xv2.w;
        }
        float br = bres[o];
        #pragma unroll
        for (int c = 0; c < 12; c++) {
            int t = t0 + c;
            hbuf[t*PO + o] = acc[c] + acc2[c] + xin[t*PO + o] + br;
        }
    }
    __syncthreads();

    for (int t = warp; t < PT; t += 4) {
        float a = hbuf[t*PO + lane], b2 = hbuf[t*PO + lane + 32];
        float s = a + b2, ss = a*a + b2*b2;
        #pragma unroll
        for (int off = 16; off; off >>= 1) {
            s  += __shfl_xor_sync(0xffffffffu, s, off);
            ss += __shfl_xor_sync(0xffffffffu, ss, off);
        }
        if (lane == 0) {
            float m = s * (1.f/64.f);
            float v = ss * (1.f/64.f) - m*m;
            red_m[t] = m;
            red_r[t] = rsqrtf(v + 1e-5f);
        }
    }
    __syncthreads();

    float* op = out + (size_t)bn * PO * PT;
    for (int i = tid; i < PO*PT; i += 128) {
        int o = i / PT, t = i % PT;
        float v = (hbuf[t*PO + o] - red_m[t]) * red_r[t] * ln_g[o] + ln_b[o];
        op[i] = fmaxf(v, 0.f);
    }
}

// ---------------- launch ----------------
extern "C" void kernel_launch(void* const* d_in, const int* in_sizes, int n_in,
                              void* d_out, int out_size) {
    const float* x      = (const float*)d_in[0];
    const float* cheb   = (const float*)d_in[1];
    const float* W1     = (const float*)d_in[2];
    const float* W2     = (const float*)d_in[3];
    const float* W3     = (const float*)d_in[4];
    const float* bsp    = (const float*)d_in[5];
    const float* Vs     = (const float*)d_in[6];
    const float* Theta  = (const float*)d_in[7];
    const float* Wres   = (const float*)d_in[8];
    const float* bres   = (const float*)d_in[9];
    const float* mg     = (const float*)d_in[10];
    const float* mb     = (const float*)d_in[11];
    const float* Win    = (const float*)d_in[12];
    const float* conv_w = (const float*)d_in[13];
    const float* conv_b = (const float*)d_in[14];
    const float* Wxp    = (const float*)d_in[15];
    const float* Wdt    = (const float*)d_in[16];
    const float* bdt    = (const float*)d_in[17];
    const float* A_log  = (const float*)d_in[18];
    const float* Dp     = (const float*)d_in[19];
    const float* Wout   = (const float*)d_in[20];
    const float* ln_g   = (const float*)d_in[21];
    const float* ln_b   = (const float*)d_in[22];
    float* out = (float*)d_out;

    k1_lhs_rhs<<<PB*PN, 64>>>(x, W1, W2, W3);
    k2_prod_sig<<<dim3(PN/64, PN/64, PB), 256>>>(bsp);
    k3_vs_gemm<<<dim3(PN/128, PN/128, PB), 256>>>(Vs);
    k4_softmax<<<dim3(PN/128, PB), 128>>>();
    k6_xtheta<<<PB*PN, 256>>>(x, Theta);
    k7_gcn_gemm<<<dim3(PJ/128, PN/128, PB), 256>>>(cheb);
    k8_mamba<<<PB*PN, 128>>>(x, mg, mb, Win, conv_w, conv_b, Wxp, Wdt, bdt,
                             A_log, Dp, Wout, Wres, bres, ln_g, ln_b, out);
}